// round 3
// baseline (speedup 1.0000x reference)
#include <cuda_runtime.h>
#include <math.h>

#define N_NODES 10000
#define N_EDGES 160000
#define BATCH 4
#define T_STEPS 16
#define HID 64
#define M_ROWS (N_NODES*BATCH)   // 40000
#define M_PAD  40064             // padded to multiple of 128 (BM)
#define KDIM 208                 // 195 real channels padded to 208

// ---------------- scratch (device globals: allocation-free rule) ----------------
__device__ float g_h [M_PAD*HID];
__device__ float g_z [M_PAD*HID];
__device__ float g_rh[M_PAD*HID];
__device__ float g_U [(size_t)M_PAD*KDIM];
__device__ float g_deg_out[N_NODES], g_deg_in[N_NODES];
__device__ int   g_cntF[N_NODES], g_cntB[N_NODES];
__device__ int   g_offF[N_NODES+1], g_offB[N_NODES+1];
__device__ int   g_srcF[N_EDGES], g_srcB[N_EDGES];
__device__ float g_wF[N_EDGES],  g_wB[N_EDGES];
__device__ float g_Wzr[KDIM*128], g_Wh[KDIM*64];
__device__ float g_bzr[128], g_bh[64];

// ---------------- preprocessing ----------------
__global__ void zero_pre() {
    int i = blockIdx.x*blockDim.x + threadIdx.x;
    if (i < N_NODES) { g_deg_out[i]=0.f; g_deg_in[i]=0.f; g_cntF[i]=0; g_cntB[i]=0; }
}
__global__ void zero_h() {
    int i = blockIdx.x*blockDim.x + threadIdx.x;
    if (i < M_PAD*HID) g_h[i] = 0.f;
}
__global__ void edge_deg(const int* __restrict__ ei, const float* __restrict__ ew) {
    int e = blockIdx.x*blockDim.x + threadIdx.x;
    if (e >= N_EDGES) return;
    int r = ei[e], c = ei[N_EDGES + e];
    float w = ew[e];
    atomicAdd(&g_deg_out[r], w);
    atomicAdd(&g_deg_in [c], w);
    atomicAdd(&g_cntF[r], 1);
    atomicAdd(&g_cntB[c], 1);
}
// single-block exclusive scan over both count arrays (also resets counts to 0)
__global__ void scan_kernel() {
    __shared__ int sb[1024];
    int t = threadIdx.x;
    for (int pass = 0; pass < 2; pass++) {
        int*       cnt = pass == 0 ? g_cntF : g_cntB;
        int*       off = pass == 0 ? g_offF : g_offB;
        int carry = 0;
        for (int base = 0; base < N_NODES; base += 1024) {
            int v = (base + t < N_NODES) ? cnt[base + t] : 0;
            sb[t] = v; __syncthreads();
            for (int o = 1; o < 1024; o <<= 1) {
                int y = (t >= o) ? sb[t - o] : 0;
                __syncthreads();
                sb[t] += y;
                __syncthreads();
            }
            if (base + t < N_NODES) { off[base + t] = carry + sb[t] - v; cnt[base + t] = 0; }
            carry += sb[1023];
            __syncthreads();
        }
        if (t == 0) off[N_NODES] = carry;
        __syncthreads();
    }
}
__global__ void edge_fill(const int* __restrict__ ei, const float* __restrict__ ew) {
    int e = blockIdx.x*blockDim.x + threadIdx.x;
    if (e >= N_EDGES) return;
    int r = ei[e], c = ei[N_EDGES + e];
    float w = ew[e];
    float dof = g_deg_out[r];
    float cf = (dof > 0.f) ? w / dof : 0.f;
    int p = g_offF[r] + atomicAdd(&g_cntF[r], 1);
    g_srcF[p] = c; g_wF[p] = cf;
    float din = g_deg_in[c];
    float cb = (din > 0.f) ? w / din : 0.f;
    int q = g_offB[c] + atomicAdd(&g_cntB[c], 1);
    g_srcB[q] = r; g_wB[q] = cb;
}

// W layout: [dir][order][c(65)][j(64)] -> ((d*2+o)*65+c)*64+j
__device__ __forceinline__ float wval(const float* W, int c, int j) {
    if (c >= 195) return 0.f;
    if (c < 65)  return W[(0*65 + c)*64 + j] + W[(2*65 + c)*64 + j];   // W[0][0]+W[1][0]
    if (c < 130) return W[(1*65 + (c-65))*64 + j];                      // W[0][1]
    return W[(3*65 + (c-130))*64 + j];                                  // W[1][1]
}
__global__ void prep_weights(const float* __restrict__ W_z, const float* __restrict__ b_z,
                             const float* __restrict__ W_r, const float* __restrict__ b_r,
                             const float* __restrict__ W_h, const float* __restrict__ b_h) {
    int tid = blockIdx.x*blockDim.x + threadIdx.x;
    if (tid < 128) g_bzr[tid] = (tid < 64) ? b_z[tid] : b_r[tid - 64];
    if (tid < 64)  g_bh[tid]  = b_h[tid];
    if (tid < KDIM*128) {
        int c = tid / 128, j = tid % 128;
        const float* W = (j < 64) ? W_z : W_r;
        g_Wzr[tid] = wval(W, c, j & 63);
    }
    int t2 = tid - KDIM*128;
    if (t2 >= 0 && t2 < KDIM*64) {
        int c = t2 / 64, j = t2 % 64;
        g_Wh[t2] = wval(W_h, c, j);
    }
}

// ---------------- per-step aggregation: builds U rows ----------------
// U channels: [0]=x, [1..64]=h(or rh), [65]=aggF_x, [66..129]=aggF_h,
//             [130]=aggB_x, [131..194]=aggB_h, [195..207]=0 (pad)
__global__ void agg_kernel(const float* __restrict__ x_dis, int t, int full) {
    const float* __restrict__ hsrc = full ? g_h : g_rh;
    int n   = blockIdx.x;
    int tid = threadIdx.x;
    int b = tid >> 6, c = tid & 63;
    int row = n*BATCH + b;
    float* Urow = g_U + (size_t)row*KDIM;
    const float* __restrict__ xb = x_dis + (size_t)(b*T_STEPS + t)*N_NODES;

    Urow[1 + c] = hsrc[row*HID + c];
    if (full) {
        if (c == 0)  Urow[0] = xb[n];
        if (c >= 51) Urow[144 + c] = 0.f;   // pads 195..207
    }

    __shared__ int   s_src[256];
    __shared__ float s_w[256];

    for (int dir = 0; dir < 2; dir++) {
        const int*   off = dir == 0 ? g_offF : g_offB;
        const int*   src = dir == 0 ? g_srcF : g_srcB;
        const float* ww  = dir == 0 ? g_wF   : g_wB;
        int e0 = off[n], e1 = off[n + 1];
        float accH = 0.f, accX = 0.f;
        for (int base = e0; base < e1; base += 256) {
            int len = min(256, e1 - base);
            __syncthreads();
            if (tid < len) { s_src[tid] = src[base + tid]; s_w[tid] = ww[base + tid]; }
            __syncthreads();
            int i = 0;
            for (; i + 4 <= len; i += 4) {
                int s0 = s_src[i], s1 = s_src[i+1], s2 = s_src[i+2], s3 = s_src[i+3];
                float w0 = s_w[i], w1 = s_w[i+1], w2 = s_w[i+2], w3 = s_w[i+3];
                float v0 = hsrc[(s0*BATCH + b)*HID + c];
                float v1 = hsrc[(s1*BATCH + b)*HID + c];
                float v2 = hsrc[(s2*BATCH + b)*HID + c];
                float v3 = hsrc[(s3*BATCH + b)*HID + c];
                accH += w0*v0 + w1*v1 + w2*v2 + w3*v3;
                if (full && c == 0) {
                    accX += w0*xb[s0] + w1*xb[s1] + w2*xb[s2] + w3*xb[s3];
                }
            }
            for (; i < len; i++) {
                int s = s_src[i]; float w = s_w[i];
                accH += w * hsrc[(s*BATCH + b)*HID + c];
                if (full && c == 0) accX += w * xb[s];
            }
        }
        int chbase = dir == 0 ? 65 : 130;
        Urow[chbase + 1 + c] = accH;
        if (full && c == 0) Urow[chbase] = accX;
    }
}

// ---------------- GEMM: [M x 208] @ [208 x NOUT], 8x8 register tile, fused epilogues ----------------
// NOUT=128 (z,r gates): z = sigmoid, rh = sigmoid(r)*h
// NOUT=64  (c gate):    h = z*h + (1-z)*tanh(c)
template<int NOUT, int NT>
__global__ void __launch_bounds__(NT) gemm_kernel() {
    constexpr int BM = 128, BK = 16;
    constexpr int CX  = NOUT / 8;            // thread cols groups (8 cols each)
    constexpr int UF4 = BM*BK/4/NT;          // float4 U loads per thread
    constexpr int WF4 = BK*NOUT/4/NT;        // float4 W loads per thread

    __shared__ float Us[BM][BK];
    __shared__ float Ws[BK][NOUT];

    int tid = threadIdx.x;
    int tx = tid % CX, ty = tid / CX;        // ty in [0,16)
    int rowBase = blockIdx.x * BM;
    int rbase = ty * 8;
    int jbase = tx * 8;
    const float* __restrict__ Wg = (NOUT == 128) ? g_Wzr : g_Wh;
    const float* __restrict__ Ug = g_U;

    float acc[8][8];
#pragma unroll
    for (int i = 0; i < 8; i++)
#pragma unroll
        for (int q = 0; q < 8; q++) acc[i][q] = 0.f;

    float4 ureg[UF4], wreg[WF4];

    // prologue: load first K tile into registers
#pragma unroll
    for (int q = 0; q < UF4; q++) {
        int idx = tid + q*NT;
        int r = idx >> 2, s = idx & 3;
        ureg[q] = *(const float4*)(Ug + (size_t)(rowBase + r)*KDIM + s*4);
    }
#pragma unroll
    for (int q = 0; q < WF4; q++) {
        int idx = tid + q*NT;
        int rr = idx / (NOUT/4), ss = idx % (NOUT/4);
        wreg[q] = *(const float4*)(Wg + (size_t)rr*NOUT + ss*4);
    }

    for (int k0 = 0; k0 < KDIM; k0 += BK) {
        // commit current registers to smem
#pragma unroll
        for (int q = 0; q < UF4; q++) {
            int idx = tid + q*NT;
            int r = idx >> 2, s = idx & 3;
            *(float4*)&Us[r][s*4] = ureg[q];
        }
#pragma unroll
        for (int q = 0; q < WF4; q++) {
            int idx = tid + q*NT;
            int rr = idx / (NOUT/4), ss = idx % (NOUT/4);
            *(float4*)&Ws[rr][ss*4] = wreg[q];
        }
        __syncthreads();

        // prefetch next K tile into registers (overlaps with compute below)
        int k1 = k0 + BK;
        if (k1 < KDIM) {
#pragma unroll
            for (int q = 0; q < UF4; q++) {
                int idx = tid + q*NT;
                int r = idx >> 2, s = idx & 3;
                ureg[q] = *(const float4*)(Ug + (size_t)(rowBase + r)*KDIM + k1 + s*4);
            }
#pragma unroll
            for (int q = 0; q < WF4; q++) {
                int idx = tid + q*NT;
                int rr = idx / (NOUT/4), ss = idx % (NOUT/4);
                wreg[q] = *(const float4*)(Wg + (size_t)(k1 + rr)*NOUT + ss*4);
            }
        }

#pragma unroll
        for (int kk = 0; kk < BK; kk++) {
            float a[8];
#pragma unroll
            for (int i = 0; i < 8; i++) a[i] = Us[rbase + i][kk];
            float4 b0 = *(float4*)&Ws[kk][jbase];
            float4 b1 = *(float4*)&Ws[kk][jbase + 4];
#pragma unroll
            for (int i = 0; i < 8; i++) {
                acc[i][0] += a[i]*b0.x; acc[i][1] += a[i]*b0.y;
                acc[i][2] += a[i]*b0.z; acc[i][3] += a[i]*b0.w;
                acc[i][4] += a[i]*b1.x; acc[i][5] += a[i]*b1.y;
                acc[i][6] += a[i]*b1.z; acc[i][7] += a[i]*b1.w;
            }
        }
        __syncthreads();
    }

    // epilogue
#pragma unroll
    for (int i = 0; i < 8; i++) {
        int row = rowBase + rbase + i;
        if (NOUT == 128) {
            if (jbase < 64) {
#pragma unroll
                for (int q = 0; q < 8; q++) {
                    int j = jbase + q;
                    float zv = 1.f / (1.f + __expf(-(acc[i][q] + g_bzr[j])));
                    g_z[row*HID + j] = zv;
                }
            } else {
#pragma unroll
                for (int q = 0; q < 8; q++) {
                    int j = jbase + q, jr = j - 64;
                    float rv = 1.f / (1.f + __expf(-(acc[i][q] + g_bzr[j])));
                    g_rh[row*HID + jr] = rv * g_h[row*HID + jr];
                }
            }
        } else {
#pragma unroll
            for (int q = 0; q < 8; q++) {
                int j = jbase + q;
                float cv = tanhf(acc[i][q] + g_bh[j]);
                float zv = g_z[row*HID + j];
                float hv = g_h[row*HID + j];
                g_h[row*HID + j] = zv*hv + (1.f - zv)*cv;
            }
        }
    }
}

// ---------------- readout (node 0 only) ----------------
__global__ void readout_kernel(const float* __restrict__ W1, const float* __restrict__ b1,
                               const float* __restrict__ W2, const float* __restrict__ b2,
                               float* __restrict__ out) {
    int tid = threadIdx.x;
    int b = tid >> 6, j = tid & 63;
    float acc = b1[j];
#pragma unroll
    for (int c = 0; c < HID; c++)
        acc += g_h[b*HID + c] * W1[c*HID + j];   // rows 0..3 of g_h are node 0
    float v = fmaxf(acc, 0.f) * W2[j];
#pragma unroll
    for (int o = 16; o > 0; o >>= 1) v += __shfl_down_sync(0xffffffff, v, o);
    __shared__ float part[8];
    if ((tid & 31) == 0) part[tid >> 5] = v;
    __syncthreads();
    if (j == 0) out[b] = part[b*2] + part[b*2 + 1] + b2[0];
}

// ---------------- launch ----------------
extern "C" void kernel_launch(void* const* d_in, const int* in_sizes, int n_in,
                              void* d_out, int out_size) {
    const float* x_dis = (const float*)d_in[0];
    const int*   ei    = (const int*)  d_in[1];
    const float* ew    = (const float*)d_in[2];
    const float* W_z   = (const float*)d_in[3];
    const float* b_z   = (const float*)d_in[4];
    const float* W_r   = (const float*)d_in[5];
    const float* b_r   = (const float*)d_in[6];
    const float* W_h   = (const float*)d_in[7];
    const float* b_h   = (const float*)d_in[8];
    const float* W_ro1 = (const float*)d_in[9];
    const float* b_ro1 = (const float*)d_in[10];
    const float* W_ro2 = (const float*)d_in[11];
    const float* b_ro2 = (const float*)d_in[12];
    float* out = (float*)d_out;

    zero_pre <<<(N_NODES + 255)/256, 256>>>();
    zero_h   <<<(M_PAD*HID + 511)/512, 512>>>();
    edge_deg <<<(N_EDGES + 255)/256, 256>>>(ei, ew);
    scan_kernel<<<1, 1024>>>();
    edge_fill<<<(N_EDGES + 255)/256, 256>>>(ei, ew);
    prep_weights<<<(KDIM*192 + 255)/256, 256>>>(W_z, b_z, W_r, b_r, W_h, b_h);

    for (int t = 0; t < T_STEPS; t++) {
        agg_kernel<<<N_NODES, 256>>>(x_dis, t, 1);
        gemm_kernel<128, 256><<<M_PAD/128, 256>>>();
        agg_kernel<<<N_NODES, 256>>>(x_dis, t, 0);
        gemm_kernel<64, 128><<<M_PAD/128, 128>>>();
    }
    readout_kernel<<<1, 256>>>(W_ro1, b_ro1, W_ro2, b_ro2, out);
}

// round 5
// speedup vs baseline: 1.1894x; 1.1894x over previous
#include <cuda_runtime.h>
#include <cuda_bf16.h>
#include <stdint.h>
#include <math.h>

#define N_NODES 10000
#define N_EDGES 160000
#define BATCH 4
#define T_STEPS 16
#define HID 64
#define M_ROWS (N_NODES*BATCH)   // 40000
#define M_PAD  40064             // multiple of 128
#define KDIM 208                 // = 13 * 16 exactly (195 real channels + 13 zero pads)
#define NKS 13                   // k16 steps

typedef uint32_t u32;

// ---------------- device scratch ----------------
__device__ float g_h [M_PAD*HID];
__device__ float g_z [M_PAD*HID];
__device__ float g_rh[M_PAD*HID];
__device__ __align__(16) __nv_bfloat16 g_Uhi[(size_t)M_PAD*KDIM];
__device__ __align__(16) __nv_bfloat16 g_Ulo[(size_t)M_PAD*KDIM];
__device__ float g_deg_out[N_NODES], g_deg_in[N_NODES];
__device__ int   g_cntF[N_NODES], g_cntB[N_NODES];
__device__ int   g_offF[N_NODES+1], g_offB[N_NODES+1];
__device__ int   g_srcF[N_EDGES], g_srcB[N_EDGES];
__device__ float g_wF[N_EDGES],  g_wB[N_EDGES];
// Prepacked B fragment tables: [ks][split][natom][lane] -> uint2 (b0,b1 regs of m16n8k16)
__device__ uint2 g_BfZr[NKS*2*16*32];   // N=128: 16 natoms
__device__ uint2 g_BfC [NKS*2*8*32];    // N=64:  8 natoms
__device__ float g_bzr[128], g_bh[64];

// ---------------- preprocessing ----------------
__global__ void zero_pre() {
    int i = blockIdx.x*blockDim.x + threadIdx.x;
    if (i < N_NODES) { g_deg_out[i]=0.f; g_deg_in[i]=0.f; g_cntF[i]=0; g_cntB[i]=0; }
}
__global__ void zero_h() {
    int i = blockIdx.x*blockDim.x + threadIdx.x;
    if (i < M_PAD*HID) g_h[i] = 0.f;
}
__global__ void zero_U() {
    size_t i = (size_t)blockIdx.x*blockDim.x + threadIdx.x;
    size_t tot = (size_t)M_PAD*KDIM/8;   // uint4 granules (KDIM*2 bytes per row, 8 bf16 per uint4)
    if (i < tot) {
        uint4 zv = make_uint4(0,0,0,0);
        ((uint4*)g_Uhi)[i] = zv;
        ((uint4*)g_Ulo)[i] = zv;
    }
}
__global__ void edge_deg(const int* __restrict__ ei, const float* __restrict__ ew) {
    int e = blockIdx.x*blockDim.x + threadIdx.x;
    if (e >= N_EDGES) return;
    int r = ei[e], c = ei[N_EDGES + e];
    float w = ew[e];
    atomicAdd(&g_deg_out[r], w);
    atomicAdd(&g_deg_in [c], w);
    atomicAdd(&g_cntF[r], 1);
    atomicAdd(&g_cntB[c], 1);
}
__global__ void scan_kernel() {
    __shared__ int sb[1024];
    int t = threadIdx.x;
    for (int pass = 0; pass < 2; pass++) {
        int* cnt = pass == 0 ? g_cntF : g_cntB;
        int* off = pass == 0 ? g_offF : g_offB;
        int carry = 0;
        for (int base = 0; base < N_NODES; base += 1024) {
            int v = (base + t < N_NODES) ? cnt[base + t] : 0;
            sb[t] = v; __syncthreads();
            for (int o = 1; o < 1024; o <<= 1) {
                int y = (t >= o) ? sb[t - o] : 0;
                __syncthreads();
                sb[t] += y;
                __syncthreads();
            }
            if (base + t < N_NODES) { off[base + t] = carry + sb[t] - v; cnt[base + t] = 0; }
            carry += sb[1023];
            __syncthreads();
        }
        if (t == 0) off[N_NODES] = carry;
        __syncthreads();
    }
}
__global__ void edge_fill(const int* __restrict__ ei, const float* __restrict__ ew) {
    int e = blockIdx.x*blockDim.x + threadIdx.x;
    if (e >= N_EDGES) return;
    int r = ei[e], c = ei[N_EDGES + e];
    float w = ew[e];
    float dof = g_deg_out[r];
    float cf = (dof > 0.f) ? w / dof : 0.f;
    int p = g_offF[r] + atomicAdd(&g_cntF[r], 1);
    g_srcF[p] = c; g_wF[p] = cf;
    float din = g_deg_in[c];
    float cb = (din > 0.f) ? w / din : 0.f;
    int q = g_offB[c] + atomicAdd(&g_cntB[c], 1);
    g_srcB[q] = r; g_wB[q] = cb;
}

// W layout: [dir][order][c(65)][j(64)]
__device__ __forceinline__ float wval(const float* W, int c, int j) {
    if (c >= 195) return 0.f;
    if (c < 65)  return W[(0*65 + c)*64 + j] + W[(2*65 + c)*64 + j];
    if (c < 130) return W[(1*65 + (c-65))*64 + j];
    return W[(3*65 + (c-130))*64 + j];
}
__device__ __forceinline__ u32 packbf(float a, float b) {
    __nv_bfloat162 t = __floats2bfloat162_rn(a, b);
    return *(u32*)&t;
}
// Build per-lane B fragment tables for mma.m16n8k16 (row.col), bf16 hi/lo split.
// B fragment lane mapping: k = (lane%4)*2 + {0,1} (+8 for reg1), n = lane/4.
__global__ void build_bfrag(const float* __restrict__ Wz, const float* __restrict__ bz,
                            const float* __restrict__ Wr, const float* __restrict__ br,
                            const float* __restrict__ Wh, const float* __restrict__ bh) {
    int idx = blockIdx.x*blockDim.x + threadIdx.x;
    if (idx < 128) g_bzr[idx] = (idx < 64) ? bz[idx] : br[idx - 64];
    if (idx < 64)  g_bh[idx] = bh[idx];

    const int ZRE = NKS*2*16*32;            // 13312
    const int CE  = NKS*2*8*32;             // 6656
    if (idx < ZRE + CE) {
        int natot = (idx < ZRE) ? 16 : 8;
        int e = (idx < ZRE) ? idx : idx - ZRE;
        int lane = e & 31;
        int na   = (e >> 5) % natot;
        int split = (e / (32*natot)) & 1;
        int ks    = e / (64*natot);
        int k0 = ks*16 + (lane & 3)*2;
        int n  = na*8 + (lane >> 2);
        float v[4];
        if (idx < ZRE) {
            const float* W = (n < 64) ? Wz : Wr;
            int j = n & 63;
            v[0] = wval(W, k0,   j); v[1] = wval(W, k0+1, j);
            v[2] = wval(W, k0+8, j); v[3] = wval(W, k0+9, j);
        } else {
            v[0] = wval(Wh, k0,   n); v[1] = wval(Wh, k0+1, n);
            v[2] = wval(Wh, k0+8, n); v[3] = wval(Wh, k0+9, n);
        }
        float p[4];
        for (int i = 0; i < 4; i++) {
            float hi = __bfloat162float(__float2bfloat16(v[i]));
            p[i] = split ? (v[i] - hi) : hi;
        }
        uint2 frag = make_uint2(packbf(p[0], p[1]), packbf(p[2], p[3]));
        if (idx < ZRE) g_BfZr[e] = frag; else g_BfC[e] = frag;
    }
}

// ---------------- aggregation: writes U rows as bf16 hi/lo splits ----------------
__device__ __forceinline__ void storeSplit(size_t idx, float v) {
    __nv_bfloat16 hi = __float2bfloat16(v);
    g_Uhi[idx] = hi;
    g_Ulo[idx] = __float2bfloat16(v - __bfloat162float(hi));
}
__global__ void agg_kernel(const float* __restrict__ x_dis, int t, int full) {
    const float* __restrict__ hsrc = full ? g_h : g_rh;
    int n   = blockIdx.x;
    int tid = threadIdx.x;
    int b = tid >> 6, c = tid & 63;
    int row = n*BATCH + b;
    size_t ub = (size_t)row * KDIM;
    const float* __restrict__ xb = x_dis + (size_t)(b*T_STEPS + t)*N_NODES;

    storeSplit(ub + 1 + c, hsrc[row*HID + c]);
    if (full && c == 0) storeSplit(ub, xb[n]);

    __shared__ int   s_src[256];
    __shared__ float s_w[256];

    for (int dir = 0; dir < 2; dir++) {
        const int*   off = dir == 0 ? g_offF : g_offB;
        const int*   src = dir == 0 ? g_srcF : g_srcB;
        const float* ww  = dir == 0 ? g_wF   : g_wB;
        int e0 = off[n], e1 = off[n + 1];
        float accH = 0.f, accX = 0.f;
        for (int base = e0; base < e1; base += 256) {
            int len = min(256, e1 - base);
            __syncthreads();
            if (tid < len) { s_src[tid] = src[base + tid]; s_w[tid] = ww[base + tid]; }
            __syncthreads();
            int i = 0;
            for (; i + 4 <= len; i += 4) {
                int s0 = s_src[i], s1 = s_src[i+1], s2 = s_src[i+2], s3 = s_src[i+3];
                float w0 = s_w[i], w1 = s_w[i+1], w2 = s_w[i+2], w3 = s_w[i+3];
                float v0 = hsrc[(s0*BATCH + b)*HID + c];
                float v1 = hsrc[(s1*BATCH + b)*HID + c];
                float v2 = hsrc[(s2*BATCH + b)*HID + c];
                float v3 = hsrc[(s3*BATCH + b)*HID + c];
                accH += w0*v0 + w1*v1 + w2*v2 + w3*v3;
                if (full && c == 0)
                    accX += w0*xb[s0] + w1*xb[s1] + w2*xb[s2] + w3*xb[s3];
            }
            for (; i < len; i++) {
                int s = s_src[i]; float w = s_w[i];
                accH += w * hsrc[(s*BATCH + b)*HID + c];
                if (full && c == 0) accX += w * xb[s];
            }
        }
        int chbase = dir == 0 ? 65 : 130;
        storeSplit(ub + chbase + 1 + c, accH);
        if (full && c == 0) storeSplit(ub + chbase, accX);
    }
}

// ---------------- HMMA GEMM: D[128 x NOUT] = U[128 x 208] * W (bf16 3-way split) -----------
// mma.sync.aligned.m16n8k16.row.col.f32.bf16.bf16.f32, fragment layouts per PTX ISA.
__device__ __forceinline__ void mma16816(float* d, const u32* a, const u32* b) {
    asm volatile("mma.sync.aligned.m16n8k16.row.col.f32.bf16.bf16.f32 "
        "{%0,%1,%2,%3}, {%4,%5,%6,%7}, {%8,%9}, {%0,%1,%2,%3};"
        : "+f"(d[0]), "+f"(d[1]), "+f"(d[2]), "+f"(d[3])
        : "r"(a[0]), "r"(a[1]), "r"(a[2]), "r"(a[3]), "r"(b[0]), "r"(b[1]));
}
__device__ __forceinline__ float sigf(float v) { return 1.f / (1.f + __expf(-v)); }

// 512 threads = 16 warps = 4 (m) x 4 (n). Block tile: 128 rows x NOUT cols.
// Warp tile: 32 rows x (NOUT/4) cols. NA = NOUT/32 natoms per warp.
template<int NOUT>
__global__ void __launch_bounds__(512) gemm_kernel() {
    constexpr int NATOT = NOUT / 8;
    constexpr int NA    = NOUT / 32;          // natoms per warp (4 for 128, 2 for 64)
    constexpr int WCOL  = NOUT / 4;           // cols per warp

    int tid = threadIdx.x, wid = tid >> 5, lane = tid & 31;
    int wm = wid & 3, wn = wid >> 2;
    int rowBase = blockIdx.x * 128;
    int rbase = rowBase + wm*32 + (lane >> 2);
    const uint2* __restrict__ Bf = (NOUT == 128) ? g_BfZr : g_BfC;

    float acc[2][NA][4];
#pragma unroll
    for (int ma = 0; ma < 2; ma++)
#pragma unroll
        for (int j = 0; j < NA; j++)
#pragma unroll
            for (int q = 0; q < 4; q++) acc[ma][j][q] = 0.f;

    for (int ks = 0; ks < NKS; ks++) {
        int k0 = ks*16 + (lane & 3)*2;
        u32 ah[2][4], al[2][4];
#pragma unroll
        for (int ma = 0; ma < 2; ma++) {
            size_t o00 = (size_t)(rbase + ma*16)     * KDIM + k0;
            size_t o10 = (size_t)(rbase + ma*16 + 8) * KDIM + k0;
            ah[ma][0] = *(const u32*)(g_Uhi + o00);
            ah[ma][1] = *(const u32*)(g_Uhi + o10);
            ah[ma][2] = *(const u32*)(g_Uhi + o00 + 8);
            ah[ma][3] = *(const u32*)(g_Uhi + o10 + 8);
            al[ma][0] = *(const u32*)(g_Ulo + o00);
            al[ma][1] = *(const u32*)(g_Ulo + o10);
            al[ma][2] = *(const u32*)(g_Ulo + o00 + 8);
            al[ma][3] = *(const u32*)(g_Ulo + o10 + 8);
        }
        uint2 bh[NA], bl[NA];
#pragma unroll
        for (int j = 0; j < NA; j++) {
            int na = wn*NA + j;
            bh[j] = Bf[((ks*2 + 0)*NATOT + na)*32 + lane];
            bl[j] = Bf[((ks*2 + 1)*NATOT + na)*32 + lane];
        }
#pragma unroll
        for (int ma = 0; ma < 2; ma++)
#pragma unroll
            for (int j = 0; j < NA; j++) {
                mma16816(acc[ma][j], ah[ma], (const u32*)&bh[j]);
                mma16816(acc[ma][j], ah[ma], (const u32*)&bl[j]);
                mma16816(acc[ma][j], al[ma], (const u32*)&bh[j]);
            }
    }

    // epilogue: D fragment (row r: d0,d1 @ col0,col0+1; row r+8: d2,d3)
#pragma unroll
    for (int ma = 0; ma < 2; ma++) {
#pragma unroll
        for (int j = 0; j < NA; j++) {
            int col = wn*WCOL + j*8 + (lane & 3)*2;
#pragma unroll
            for (int half = 0; half < 2; half++) {
                int row = rbase + ma*16 + half*8;
                float d0 = acc[ma][j][half*2], d1 = acc[ma][j][half*2 + 1];
                if (NOUT == 128) {
                    if (col < 64) {
                        float2 zv = make_float2(sigf(d0 + g_bzr[col]), sigf(d1 + g_bzr[col+1]));
                        *(float2*)&g_z[row*HID + col] = zv;
                    } else {
                        int jr = col - 64;
                        float2 hv = *(const float2*)&g_h[row*HID + jr];
                        float2 rv = make_float2(sigf(d0 + g_bzr[col]) * hv.x,
                                                sigf(d1 + g_bzr[col+1]) * hv.y);
                        *(float2*)&g_rh[row*HID + jr] = rv;
                    }
                } else {
                    float c0 = tanhf(d0 + g_bh[col]);
                    float c1 = tanhf(d1 + g_bh[col+1]);
                    float2 zv = *(const float2*)&g_z[row*HID + col];
                    float2 hv = *(const float2*)&g_h[row*HID + col];
                    float2 nh = make_float2(zv.x*hv.x + (1.f - zv.x)*c0,
                                            zv.y*hv.y + (1.f - zv.y)*c1);
                    *(float2*)&g_h[row*HID + col] = nh;
                }
            }
        }
    }
}

// ---------------- readout (node 0 only) ----------------
__global__ void readout_kernel(const float* __restrict__ W1, const float* __restrict__ b1,
                               const float* __restrict__ W2, const float* __restrict__ b2,
                               float* __restrict__ out) {
    int tid = threadIdx.x;
    int b = tid >> 6, j = tid & 63;
    float acc = b1[j];
#pragma unroll
    for (int c = 0; c < HID; c++)
        acc += g_h[b*HID + c] * W1[c*HID + j];
    float v = fmaxf(acc, 0.f) * W2[j];
#pragma unroll
    for (int o = 16; o > 0; o >>= 1) v += __shfl_down_sync(0xffffffff, v, o);
    __shared__ float part[8];
    if ((tid & 31) == 0) part[tid >> 5] = v;
    __syncthreads();
    if (j == 0) out[b] = part[b*2] + part[b*2 + 1] + b2[0];
}

// ---------------- launch ----------------
extern "C" void kernel_launch(void* const* d_in, const int* in_sizes, int n_in,
                              void* d_out, int out_size) {
    const float* x_dis = (const float*)d_in[0];
    const int*   ei    = (const int*)  d_in[1];
    const float* ew    = (const float*)d_in[2];
    const float* W_z   = (const float*)d_in[3];
    const float* b_z   = (const float*)d_in[4];
    const float* W_r   = (const float*)d_in[5];
    const float* b_r   = (const float*)d_in[6];
    const float* W_h   = (const float*)d_in[7];
    const float* b_h   = (const float*)d_in[8];
    const float* W_ro1 = (const float*)d_in[9];
    const float* b_ro1 = (const float*)d_in[10];
    const float* W_ro2 = (const float*)d_in[11];
    const float* b_ro2 = (const float*)d_in[12];
    float* out = (float*)d_out;

    zero_pre <<<(N_NODES + 255)/256, 256>>>();
    zero_h   <<<(M_PAD*HID + 511)/512, 512>>>();
    zero_U   <<<((int)((size_t)M_PAD*KDIM/8) + 255)/256, 256>>>();
    edge_deg <<<(N_EDGES + 255)/256, 256>>>(ei, ew);
    scan_kernel<<<1, 1024>>>();
    edge_fill<<<(N_EDGES + 255)/256, 256>>>(ei, ew);
    build_bfrag<<<(NKS*2*16*32 + NKS*2*8*32 + 255)/256, 256>>>(W_z, b_z, W_r, b_r, W_h, b_h);

    for (int t = 0; t < T_STEPS; t++) {
        agg_kernel<<<N_NODES, 256>>>(x_dis, t, 1);
        gemm_kernel<128><<<M_PAD/128, 512>>>();
        agg_kernel<<<N_NODES, 256>>>(x_dis, t, 0);
        gemm_kernel<64><<<M_PAD/128, 512>>>();
    }
    readout_kernel<<<1, 256>>>(W_ro1, b_ro1, W_ro2, b_ro2, out);
}